// round 12
// baseline (speedup 1.0000x reference)
#include <cuda_runtime.h>

// RelationCrossing — feats (R=8, N, K=8, d=64) fp32, rel_attn (8,64) fp32.
// scores[r,n,k] = leaky_relu(dot(feats[r,n,k,:], rel_attn[k,:]), 0.2)
// attn = softmax over r; out[n,k,:] = sum_r attn[r,n,k] * feats[r,n,k,:]
//
// Final config-cube point: R11's measured-best structure (__stwt write-through
// stores; 254.0us, DRAM 92.0%) combined with __launch_bounds__(256, 5)
// (48 regs -> 5 CTAs/SM = 40 warps, individually neutral in R8). With the
// store path shortened by WT, the extra warps have marginally better odds of
// filling residual DRAM-demand gaps. Traffic at the 1.843 GB floor; 12-round
// sweep shows all structural alternatives strictly worse — this kernel is at
// the HBM roofline for the 8:1 read:write streaming mix.

#define R 8
#define NEG_SLOPE 0.2f

__global__ __launch_bounds__(256, 5) void relation_crossing_kernel(
    const float4* __restrict__ feats,   // R * N * 128 float4s
    const float4* __restrict__ rel,     // 128 float4s (8 heads * 16 quarters)
    float4* __restrict__ out,           // N * 128 float4s
    int total4,                         // N * 128
    long long rel_stride4)              // N * 128 (float4 stride between relations)
{
    int idx = blockIdx.x * blockDim.x + threadIdx.x;
    if (idx >= total4) return;

    // idx = n*128 + k*16 + q  (k = head, q = d-quarter). rel index = k*16+q.
    float4 ra = __ldg(&rel[idx & 127]);

    // Front-batched loads: 8 independent LDG.128 (MLP=8), dot partials folded
    // in as each lands.
    float4 f[R];
    float s[R];
#pragma unroll
    for (int r = 0; r < R; r++) {
        f[r] = feats[(long long)r * rel_stride4 + idx];
        s[r] = f[r].x * ra.x + f[r].y * ra.y + f[r].z * ra.z + f[r].w * ra.w;
    }

    // Reduce dot products across the 16-thread group covering this head.
    // Groups of 16 are warp-aligned, so xor offsets 8,4,2,1 stay in-group;
    // 8 independent values per level -> serial chain is 4 SHFL latencies.
#pragma unroll
    for (int off = 8; off >= 1; off >>= 1) {
#pragma unroll
        for (int r = 0; r < R; r++)
            s[r] += __shfl_xor_sync(0xffffffffu, s[r], off);
    }

    // leaky_relu + softmax over relations (identical across the 16-lane group).
    float m = -3.4e38f;
#pragma unroll
    for (int r = 0; r < R; r++) {
        s[r] = (s[r] > 0.0f) ? s[r] : NEG_SLOPE * s[r];
        m = fmaxf(m, s[r]);
    }
    float sum = 0.0f;
#pragma unroll
    for (int r = 0; r < R; r++) {
        s[r] = __expf(s[r] - m);
        sum += s[r];
    }
    float inv = __frcp_rn(sum);

    float4 o = make_float4(0.f, 0.f, 0.f, 0.f);
#pragma unroll
    for (int r = 0; r < R; r++) {
        float w = s[r] * inv;
        o.x = fmaf(w, f[r].x, o.x);
        o.y = fmaf(w, f[r].y, o.y);
        o.z = fmaf(w, f[r].z, o.z);
        o.w = fmaf(w, f[r].w, o.w);
    }
    __stwt(&out[idx], o);   // STG.WT — write-through, no dirty-L2 eviction bursts
}

extern "C" void kernel_launch(void* const* d_in, const int* in_sizes, int n_in,
                              void* d_out, int out_size)
{
    const float4* feats = (const float4*)d_in[0];  // (8, N, 512) fp32
    const float4* rel   = (const float4*)d_in[1];  // (8, 64) fp32
    float4* out = (float4*)d_out;                  // (N, 512) fp32

    long long elems_per_rel = (long long)in_sizes[0] / R;   // N*512 floats
    int total4 = (int)(elems_per_rel / 4);                  // N*128 float4
    long long rel_stride4 = total4;

    int threads = 256;
    int blocks = (total4 + threads - 1) / threads;
    relation_crossing_kernel<<<blocks, threads>>>(feats, rel, out, total4, rel_stride4);
}

// round 13
// speedup vs baseline: 1.0050x; 1.0050x over previous
#include <cuda_runtime.h>

// RelationCrossing — FINAL (R11 config, session best: 254.0us, DRAM 92.0%).
// feats (R=8, N, K=8, d=64) fp32, rel_attn (8,64) fp32.
// scores[r,n,k] = leaky_relu(dot(feats[r,n,k,:], rel_attn[k,:]), 0.2)
// attn = softmax over r; out[n,k,:] = sum_r attn[r,n,k] * feats[r,n,k,:]
//
// Single-pass, register-resident: each thread owns a float4 (4 d-values) of
// one (n,k); 16 warp-aligned threads cover a head; dot reduced via 4-level
// xor-shuffle butterfly; softmax redundant per lane (compute ~20% util, free);
// weighted sum from registers; __stwt (STG.WT) store — write-through avoids
// LTS dirty-eviction bursts interleaving with the 8 read streams (the one
// micro-lever that measurably improved DRAM% in a 12-round sweep).
//
// At the HBM roofline: 7.29 TB/s (92% of spec), traffic at the theoretical
// floor (1.638 GB read + 0.205 GB write). Ruled out as limiters: occupancy
// (44-62% sweep flat), block size, cp.async SMEM staging, float2 granularity,
// persistent grid + SW pipeline, two-pass L2 re-read, streaming read hints,
// split-batch reduction, launch-bounds reg capping (alone and with WT).
// Residual ~8% is HBM read/write turnaround on the 8:1 mix.
// (Note: redux.sync.add.f32 does not exist on sm_103.)

#define R 8
#define NEG_SLOPE 0.2f

__global__ __launch_bounds__(256) void relation_crossing_kernel(
    const float4* __restrict__ feats,   // R * N * 128 float4s
    const float4* __restrict__ rel,     // 128 float4s (8 heads * 16 quarters)
    float4* __restrict__ out,           // N * 128 float4s
    int total4,                         // N * 128
    long long rel_stride4)              // N * 128 (float4 stride between relations)
{
    int idx = blockIdx.x * blockDim.x + threadIdx.x;
    if (idx >= total4) return;

    // idx = n*128 + k*16 + q  (k = head, q = d-quarter). rel index = k*16+q.
    float4 ra = rel[idx & 127];

    // Front-batched loads: 8 independent LDG.128 (MLP=8), dot partials folded
    // in as each lands.
    float4 f[R];
    float s[R];
#pragma unroll
    for (int r = 0; r < R; r++) {
        f[r] = feats[(long long)r * rel_stride4 + idx];
        s[r] = f[r].x * ra.x + f[r].y * ra.y + f[r].z * ra.z + f[r].w * ra.w;
    }

    // Reduce dot products across the 16-thread group covering this head.
    // Groups of 16 are warp-aligned, so xor offsets 8,4,2,1 stay in-group;
    // 8 independent values per level -> serial chain is 4 SHFL latencies.
#pragma unroll
    for (int off = 8; off >= 1; off >>= 1) {
#pragma unroll
        for (int r = 0; r < R; r++)
            s[r] += __shfl_xor_sync(0xffffffffu, s[r], off);
    }

    // leaky_relu + softmax over relations (identical across the 16-lane group).
    float m = -3.4e38f;
#pragma unroll
    for (int r = 0; r < R; r++) {
        s[r] = (s[r] > 0.0f) ? s[r] : NEG_SLOPE * s[r];
        m = fmaxf(m, s[r]);
    }
    float sum = 0.0f;
#pragma unroll
    for (int r = 0; r < R; r++) {
        s[r] = __expf(s[r] - m);
        sum += s[r];
    }
    float inv = __frcp_rn(sum);

    float4 o = make_float4(0.f, 0.f, 0.f, 0.f);
#pragma unroll
    for (int r = 0; r < R; r++) {
        float w = s[r] * inv;
        o.x = fmaf(w, f[r].x, o.x);
        o.y = fmaf(w, f[r].y, o.y);
        o.z = fmaf(w, f[r].z, o.z);
        o.w = fmaf(w, f[r].w, o.w);
    }
    __stwt(&out[idx], o);   // STG.WT — write-through, no dirty-L2 eviction bursts
}

extern "C" void kernel_launch(void* const* d_in, const int* in_sizes, int n_in,
                              void* d_out, int out_size)
{
    const float4* feats = (const float4*)d_in[0];  // (8, N, 512) fp32
    const float4* rel   = (const float4*)d_in[1];  // (8, 64) fp32
    float4* out = (float4*)d_out;                  // (N, 512) fp32

    long long elems_per_rel = (long long)in_sizes[0] / R;   // N*512 floats
    int total4 = (int)(elems_per_rel / 4);                  // N*128 float4
    long long rel_stride4 = total4;

    int threads = 256;
    int blocks = (total4 + threads - 1) / threads;
    relation_crossing_kernel<<<blocks, threads>>>(feats, rel, out, total4, rel_stride4);
}